// round 3
// baseline (speedup 1.0000x reference)
#include <cuda_runtime.h>
#include <stdint.h>

// ---------------------------------------------------------------------------
// PairLoss:  result = ( sum_{gt<0.5} exp(p) * sum_{gt>0.5} exp(-p) - n_neg ) / 2
// Pure streaming reduction over 2 x 128MB fp32 arrays -> HBM-bound (~40us floor).
// Deterministic two-pass reduction (no float atomics), graph-capturable,
// allocation-free (__device__ global partials buffer).
// ---------------------------------------------------------------------------

#define NBLOCKS 1184
#define NTHREADS 256

// 3 partials per block: sum_exp_neg, sum_exp_minus_pos, n_neg
__device__ double g_part[3 * NBLOCKS];

__device__ __forceinline__ void accum_one(float p, float g, float& s_neg,
                                          float& s_pos, float& cnt) {
    bool pos = g > 0.5f;
    float e = __expf(pos ? -p : p);
    if (pos) s_pos += e;
    else { s_neg += e; cnt += 1.0f; }
}

__device__ __forceinline__ void block_reduce_store(float s_neg, float s_pos,
                                                   float cnt) {
    __shared__ float sh[3][NTHREADS / 32];
    int lane = threadIdx.x & 31;
    int warp = threadIdx.x >> 5;

    #pragma unroll
    for (int off = 16; off > 0; off >>= 1) {
        s_neg += __shfl_down_sync(0xffffffffu, s_neg, off);
        s_pos += __shfl_down_sync(0xffffffffu, s_pos, off);
        cnt   += __shfl_down_sync(0xffffffffu, cnt,   off);
    }
    if (lane == 0) {
        sh[0][warp] = s_neg;
        sh[1][warp] = s_pos;
        sh[2][warp] = cnt;
    }
    __syncthreads();
    if (warp == 0) {
        const int nw = NTHREADS / 32;
        float a = (lane < nw) ? sh[0][lane] : 0.0f;
        float b = (lane < nw) ? sh[1][lane] : 0.0f;
        float c = (lane < nw) ? sh[2][lane] : 0.0f;
        #pragma unroll
        for (int off = 16; off > 0; off >>= 1) {
            a += __shfl_down_sync(0xffffffffu, a, off);
            b += __shfl_down_sync(0xffffffffu, b, off);
            c += __shfl_down_sync(0xffffffffu, c, off);
        }
        if (lane == 0) {
            g_part[blockIdx.x]               = (double)a;
            g_part[NBLOCKS + blockIdx.x]     = (double)b;
            g_part[2 * NBLOCKS + blockIdx.x] = (double)c;
        }
    }
}

// Vectorized path: requires 16B-aligned pointers (checked on host).
__global__ void __launch_bounds__(NTHREADS)
pairloss_reduce_vec4(const float4* __restrict__ p4,
                     const float4* __restrict__ g4,
                     const float* __restrict__ pred,
                     const float* __restrict__ gt, int n) {
    float s_neg = 0.0f, s_pos = 0.0f, cnt = 0.0f;
    int n4 = n >> 2;
    int stride = gridDim.x * blockDim.x;

    for (int i = blockIdx.x * blockDim.x + threadIdx.x; i < n4; i += stride) {
        float4 p = p4[i];
        float4 g = g4[i];
        accum_one(p.x, g.x, s_neg, s_pos, cnt);
        accum_one(p.y, g.y, s_neg, s_pos, cnt);
        accum_one(p.z, g.z, s_neg, s_pos, cnt);
        accum_one(p.w, g.w, s_neg, s_pos, cnt);
    }
    // scalar tail
    for (int i = (n4 << 2) + blockIdx.x * blockDim.x + threadIdx.x; i < n;
         i += stride) {
        accum_one(pred[i], gt[i], s_neg, s_pos, cnt);
    }
    block_reduce_store(s_neg, s_pos, cnt);
}

// Fallback scalar path (unaligned inputs — not expected, but trap-safe).
__global__ void __launch_bounds__(NTHREADS)
pairloss_reduce_scalar(const float* __restrict__ pred,
                       const float* __restrict__ gt, int n) {
    float s_neg = 0.0f, s_pos = 0.0f, cnt = 0.0f;
    int stride = gridDim.x * blockDim.x;
    for (int i = blockIdx.x * blockDim.x + threadIdx.x; i < n; i += stride)
        accum_one(pred[i], gt[i], s_neg, s_pos, cnt);
    block_reduce_store(s_neg, s_pos, cnt);
}

__global__ void __launch_bounds__(NTHREADS)
pairloss_final_kernel(float* __restrict__ out) {
    __shared__ double sh[3][NTHREADS / 32];
    int lane = threadIdx.x & 31;
    int warp = threadIdx.x >> 5;

    double a = 0.0, b = 0.0, c = 0.0;
    for (int i = threadIdx.x; i < NBLOCKS; i += NTHREADS) {
        a += g_part[i];
        b += g_part[NBLOCKS + i];
        c += g_part[2 * NBLOCKS + i];
    }
    #pragma unroll
    for (int off = 16; off > 0; off >>= 1) {
        a += __shfl_down_sync(0xffffffffu, a, off);
        b += __shfl_down_sync(0xffffffffu, b, off);
        c += __shfl_down_sync(0xffffffffu, c, off);
    }
    if (lane == 0) { sh[0][warp] = a; sh[1][warp] = b; sh[2][warp] = c; }
    __syncthreads();
    if (warp == 0) {
        const int nw = NTHREADS / 32;
        a = (lane < nw) ? sh[0][lane] : 0.0;
        b = (lane < nw) ? sh[1][lane] : 0.0;
        c = (lane < nw) ? sh[2][lane] : 0.0;
        #pragma unroll
        for (int off = 16; off > 0; off >>= 1) {
            a += __shfl_down_sync(0xffffffffu, a, off);
            b += __shfl_down_sync(0xffffffffu, b, off);
            c += __shfl_down_sync(0xffffffffu, c, off);
        }
        if (lane == 0) {
            out[0] = (float)((a * b - c) * 0.5);
        }
    }
}

extern "C" void kernel_launch(void* const* d_in, const int* in_sizes, int n_in,
                              void* d_out, int out_size) {
    const float* pred = (const float*)d_in[0];
    const float* gt   = (const float*)d_in[1];
    float* out = (float*)d_out;
    int n = in_sizes[0];

    bool aligned = (((uintptr_t)pred | (uintptr_t)gt) & 0xF) == 0;
    if (aligned) {
        pairloss_reduce_vec4<<<NBLOCKS, NTHREADS>>>(
            (const float4*)pred, (const float4*)gt, pred, gt, n);
    } else {
        pairloss_reduce_scalar<<<NBLOCKS, NTHREADS>>>(pred, gt, n);
    }
    pairloss_final_kernel<<<1, NTHREADS>>>(out);
}